// round 3
// baseline (speedup 1.0000x reference)
#include <cuda_runtime.h>

#define R   5
#define E   50000
#define NUU 20000
#define NII 20000
#define NF  4
#define DN  16
#define DR  64
#define DOUT 64

// ---------------- scratch (allocation-free: __device__ globals) ----------------
__device__ float4 g_hu[R*NUU*4];     // hu[r,n,0:16]
__device__ float4 g_hi[R*NII*4];
__device__ float  g_blend[R*E];
__device__ float4 g_rfw[R*E*4];      // rfw[r,e,0:16]
__device__ float4 g_rfr[R*E*4];
__device__ float  g_norm_u[NUU];
__device__ float  g_norm_i[NII];
__device__ float4 g_umsg[NUU*4];
__device__ float4 g_imsg[NII*4];

__device__ __forceinline__ float dot4(float4 a, float4 b){
    return a.x*b.x + a.y*b.y + a.z*b.z + a.w*b.w;
}

__device__ __forceinline__ void red_add_v4(float4* addr, float4 v){
    asm volatile("red.global.add.v4.f32 [%0], {%1,%2,%3,%4};"
                 :: "l"(addr), "f"(v.x), "f"(v.y), "f"(v.z), "f"(v.w)
                 : "memory");
}

// ---------------- K0: zero accumulators ----------------
__global__ void __launch_bounds__(256) k_zero(){
    int i = blockIdx.x*256 + threadIdx.x;
    if (i < NUU) g_norm_u[i] = 0.f;
    if (i < NII) g_norm_i[i] = 0.f;
    float4 z = make_float4(0.f,0.f,0.f,0.f);
    if (i < NUU*4) g_umsg[i] = z;
    if (i < NII*4) g_imsg[i] = z;
}

// ---------------- K1: hu/hi = node_h[k] @ node_w^T ----------------
__global__ void __launch_bounds__(256) k_nodes(
    const float* __restrict__ user_h, const float* __restrict__ item_h,
    const float* __restrict__ w_fwd,  const float* __restrict__ w_rev,
    const int*   __restrict__ kp)
{
    __shared__ float Ws[DN*DN];
    int r = blockIdx.y, side = blockIdx.z;
    const float* W = side ? w_rev : w_fwd;
    Ws[threadIdx.x] = W[r*DN*DN + threadIdx.x];
    __syncthreads();
    int n = blockIdx.x*256 + threadIdx.x;
    if (n >= NUU) return;
    int kv = __ldg(kp);
    const float* hp = (side ? item_h : user_h) + ((size_t)(kv*R + r)*NUU + n)*DN;
    const float4* h4 = (const float4*)hp;
    float h[16];
    #pragma unroll
    for (int j=0;j<4;j++){
        float4 v = h4[j];
        h[4*j]=v.x; h[4*j+1]=v.y; h[4*j+2]=v.z; h[4*j+3]=v.w;
    }
    float4* out = (side ? g_hi : g_hu) + ((size_t)r*NUU + n)*4;
    #pragma unroll
    for (int q=0;q<4;q++){
        float acc[4];
        #pragma unroll
        for (int t=0;t<4;t++){
            int o = q*4+t;
            float a = 0.f;
            #pragma unroll
            for (int d=0; d<16; d++) a += h[d]*Ws[o*16+d];
            acc[t] = a;
        }
        out[q] = make_float4(acc[0],acc[1],acc[2],acc[3]);
    }
}

// ---------------- K2: per-edge blended + rfw/rfr + norm accumulation ----------------
__global__ void __launch_bounds__(256) k_edge(
    const float* __restrict__ user_h,    const float* __restrict__ item_h,
    const float* __restrict__ user_hsum, const float* __restrict__ item_hsum,
    const float* __restrict__ review_feat, const float* __restrict__ prototypes,
    const float* __restrict__ eta,
    const float* __restrict__ rw_fwd,    const float* __restrict__ rw_rev,
    const int*   __restrict__ edge_src,  const int* __restrict__ edge_dst,
    const int*   __restrict__ kp)
{
    __shared__ float4 Wf[DN*DR/4];   // 256 float4
    __shared__ float4 Wr[DN*DR/4];
    __shared__ float4 Pr[NF*DR/4];   // 64 float4
    int r   = blockIdx.y;
    int tid = threadIdx.x;
    Wf[tid] = ((const float4*)(rw_fwd + (size_t)r*DN*DR))[tid];
    Wr[tid] = ((const float4*)(rw_rev + (size_t)r*DN*DR))[tid];
    if (tid < NF*DR/4) Pr[tid] = ((const float4*)prototypes)[tid];
    __syncthreads();

    int e = blockIdx.x*256 + tid;
    if (e >= E) return;
    int kv  = __ldg(kp);
    int idx = r*E + e;
    int src = __ldg(edge_src + idx);
    int dst = __ldg(edge_dst + idx);

    // ---- sim_k: cosine of user_h[k][r][src] vs item_h[k][r][dst], /TAU ----
    const float4* u4 = (const float4*)(user_h + ((size_t)(kv*R + r)*NUU + src)*DN);
    const float4* v4 = (const float4*)(item_h + ((size_t)(kv*R + r)*NII + dst)*DN);
    float uu=0.f, ii=0.f, ui=0.f;
    #pragma unroll
    for (int j=0;j<4;j++){
        float4 a = u4[j], b = v4[j];
        uu += dot4(a,a); ii += dot4(b,b); ui += dot4(a,b);
    }
    float den = fmaxf(sqrtf(uu),1e-12f) * fmaxf(sqrtf(ii),1e-12f);
    float sim_k = (ui/den) * 2.0f;   // 1/TAU = 2

    // ---- sim_all over NF factors ----
    const float4* ru = (const float4*)(user_hsum + ((size_t)(r*NUU+src))*NF*DN);
    const float4* ci = (const float4*)(item_hsum + ((size_t)(r*NII+dst))*NF*DN);
    float dS = 0.f;
    #pragma unroll
    for (int f=0; f<NF; f++){
        float s = 0.f;
        #pragma unroll
        for (int j=0;j<4;j++) s += dot4(ru[f*4+j], ci[f*4+j]);
        dS += __expf(s*2.0f);
    }
    float exp_sim = __expf(sim_k)/dS;

    // ---- anchors over review_feat ----
    const float4* rf = (const float4*)(review_feat + (size_t)idx*NF*DR);
    float dA=0.f, nA=0.f;
    #pragma unroll
    for (int f=0; f<NF; f++){
        float a = 0.f;
        #pragma unroll
        for (int j=0;j<16;j++) a += dot4(rf[f*16+j], Pr[f*16+j]);
        a *= 2.0f;
        dA += __expf(a);
        if (f==kv) nA = a;
    }
    float exp_anchor = __expf(nA)/dA;

    float et = __ldg(eta + idx);
    float g  = 1.0f/(1.0f + __expf(-et));
    float blended = g*exp_anchor + (1.0f-g)*exp_sim;
    g_blend[idx] = blended;
    atomicAdd(&g_norm_u[src], blended);
    atomicAdd(&g_norm_i[dst], blended);

    // ---- rfw/rfr: rf_k (64) x review_w (16x64) ----
    const float4* rfk = rf + kv*16;   // L1-hot (touched in anchor pass)
    float accw[16], accr[16];
    #pragma unroll
    for (int o=0;o<16;o++){ accw[o]=0.f; accr[o]=0.f; }
    #pragma unroll 4
    for (int j=0;j<16;j++){
        float4 v = __ldg(&rfk[j]);
        #pragma unroll
        for (int o=0;o<16;o++){
            accw[o] += dot4(v, Wf[o*16+j]);
            accr[o] += dot4(v, Wr[o*16+j]);
        }
    }
    float4* ow = &g_rfw[(size_t)idx*4];
    float4* orr= &g_rfr[(size_t)idx*4];
    #pragma unroll
    for (int q=0;q<4;q++){
        ow[q]  = make_float4(accw[4*q],accw[4*q+1],accw[4*q+2],accw[4*q+3]);
        orr[q] = make_float4(accr[4*q],accr[4*q+1],accr[4*q+2],accr[4*q+3]);
    }
}

// ---------------- K3: w, int_dist, message scatter ----------------
__global__ void __launch_bounds__(256) k_edge3(
    const int* __restrict__ edge_src, const int* __restrict__ edge_dst,
    float* __restrict__ out)
{
    int r = blockIdx.y;
    int e = blockIdx.x*256 + threadIdx.x;
    if (e >= E) return;
    int idx = r*E + e;
    int src = __ldg(edge_src + idx);
    int dst = __ldg(edge_dst + idx);
    float b = g_blend[idx];
    float w = b * rsqrtf(g_norm_u[src]*g_norm_i[dst]);
    out[NUU*DOUT + NII*DOUT + idx] = w;   // int_dist

    const float4* hu = &g_hu[((size_t)r*NUU + src)*4];
    const float4* rw = &g_rfw[(size_t)idx*4];
    float4* im = &g_imsg[(size_t)dst*4];
    #pragma unroll
    for (int q=0;q<4;q++){
        float4 a = hu[q], c = rw[q];
        red_add_v4(&im[q], make_float4((a.x+c.x)*w,(a.y+c.y)*w,(a.z+c.z)*w,(a.w+c.w)*w));
    }
    const float4* hi = &g_hi[((size_t)r*NII + dst)*4];
    const float4* rr = &g_rfr[(size_t)idx*4];
    float4* um = &g_umsg[(size_t)src*4];
    #pragma unroll
    for (int q=0;q<4;q++){
        float4 a = hi[q], c = rr[q];
        red_add_v4(&um[q], make_float4((a.x+c.x)*w,(a.y+c.y)*w,(a.z+c.z)*w,(a.w+c.w)*w));
    }
}

// ---------------- K4: leaky_relu + FC epilogue ----------------
__global__ void __launch_bounds__(256) k_fc(
    const float* __restrict__ ufc_w, const float* __restrict__ ufc_b,
    const float* __restrict__ ifc_w, const float* __restrict__ ifc_b,
    float* __restrict__ out)
{
    int side = blockIdx.y;
    int idx  = blockIdx.x*256 + threadIdx.x;   // < NUU*DOUT
    int n = idx >> 6;
    int o = idx & 63;
    const float* W = side ? ifc_w : ufc_w;
    const float* B = side ? ifc_b : ufc_b;
    const float* msg = (const float*)(side ? g_imsg : g_umsg) + (size_t)n*DN;
    float acc = __ldg(B + o);
    #pragma unroll
    for (int j=0;j<DN;j++){
        float x = msg[j];
        x = (x > 0.f) ? x : 0.1f*x;
        acc += x * __ldg(W + o*DN + j);
    }
    out[(size_t)side*NUU*DOUT + (size_t)n*DOUT + o] = acc;
}

// ---------------- launch ----------------
extern "C" void kernel_launch(void* const* d_in, const int* in_sizes, int n_in,
                              void* d_out, int out_size)
{
    const float* user_h      = (const float*)d_in[0];
    const float* item_h      = (const float*)d_in[1];
    const float* user_hsum   = (const float*)d_in[2];
    const float* item_hsum   = (const float*)d_in[3];
    const float* review_feat = (const float*)d_in[4];
    const float* prototypes  = (const float*)d_in[5];
    const float* eta         = (const float*)d_in[6];
    const float* node_w_fwd  = (const float*)d_in[7];
    const float* review_w_fwd= (const float*)d_in[8];
    const float* node_w_rev  = (const float*)d_in[9];
    const float* review_w_rev= (const float*)d_in[10];
    const float* ufc_w       = (const float*)d_in[11];
    const float* ufc_b       = (const float*)d_in[12];
    const float* ifc_w       = (const float*)d_in[13];
    const float* ifc_b       = (const float*)d_in[14];
    const int*   edge_src    = (const int*)d_in[15];
    const int*   edge_dst    = (const int*)d_in[16];
    const int*   kp          = (const int*)d_in[17];
    float* out = (float*)d_out;

    k_zero <<<(NUU*4 + 255)/256, 256>>>();
    k_nodes<<<dim3((NUU+255)/256, R, 2), 256>>>(user_h, item_h, node_w_fwd, node_w_rev, kp);
    k_edge <<<dim3((E+255)/256, R), 256>>>(user_h, item_h, user_hsum, item_hsum,
                                           review_feat, prototypes, eta,
                                           review_w_fwd, review_w_rev,
                                           edge_src, edge_dst, kp);
    k_edge3<<<dim3((E+255)/256, R), 256>>>(edge_src, edge_dst, out);
    k_fc   <<<dim3((NUU*DOUT)/256, 2), 256>>>(ufc_w, ufc_b, ifc_w, ifc_b, out);
}